// round 4
// baseline (speedup 1.0000x reference)
#include <cuda_runtime.h>
#include <math.h>

#define N_MAX   32768
#define EMAX    600000
#define FULL_M  0xffffffffu
#define NEG_SLOPE 0.2f
#define EPS_    1e-16f

// ---------------- device scratch (static: no allocation allowed) ----------------
__device__ int   g_counts[N_MAX];
__device__ int   g_cursor[N_MAX];
__device__ int   g_rowptr[N_MAX + 1];
__device__ int   g_csr_src[EMAX];
__device__ __align__(16) float g_h1[N_MAX * 128];
__device__ __align__(16) float g_act1[N_MAX * 128];
__device__ __align__(16) float g_h2[N_MAX * 128];
__device__ float4 g_as1[N_MAX];
__device__ float4 g_ad1[N_MAX];
__device__ float  g_as2[N_MAX];
__device__ float  g_ad2[N_MAX];

__device__ __forceinline__ float lrelu(float v) { return v > 0.f ? v : NEG_SLOPE * v; }

// ---------------- CSR construction ----------------
__global__ void init_kernel(int n) {
    int i = blockIdx.x * blockDim.x + threadIdx.x;
    if (i < n) { g_counts[i] = 1; g_cursor[i] = 0; }  // count=1: implicit self loop
}

__global__ void hist_kernel(const int* __restrict__ ei, int E) {
    int e = blockIdx.x * blockDim.x + threadIdx.x;
    if (e < E) atomicAdd(&g_counts[ei[E + e]], 1);    // row 1 = dst
}

__global__ void scan_kernel(int n) {
    __shared__ int wsum[32];
    int tid = threadIdx.x, lane = tid & 31, wid = tid >> 5;
    if (tid == 0) g_rowptr[0] = 0;
    int carry = 0;
    for (int base = 0; base < n; base += 1024) {
        int i = base + tid;
        int x = (i < n) ? g_counts[i] : 0;
        #pragma unroll
        for (int d = 1; d < 32; d <<= 1) {
            int t = __shfl_up_sync(FULL_M, x, d);
            if (lane >= d) x += t;
        }
        if (lane == 31) wsum[wid] = x;
        __syncthreads();
        if (wid == 0) {
            int y = wsum[lane];
            #pragma unroll
            for (int d = 1; d < 32; d <<= 1) {
                int t = __shfl_up_sync(FULL_M, y, d);
                if (lane >= d) y += t;
            }
            wsum[lane] = y;
        }
        __syncthreads();
        int pre  = (wid > 0) ? wsum[wid - 1] : 0;
        int incl = x + pre + carry;
        if (i < n) g_rowptr[i + 1] = incl;
        carry += wsum[31];
        __syncthreads();
    }
}

__global__ void scatter_kernel(const int* __restrict__ ei, int E, int n) {
    int t = blockIdx.x * blockDim.x + threadIdx.x;
    if (t >= E + n) return;
    int d, s;
    if (t < E) { s = ei[t]; d = ei[E + t]; }
    else       { d = t - E; s = d; }                  // self loop
    int pos = g_rowptr[d] + atomicAdd(&g_cursor[d], 1);
    g_csr_src[pos] = s;
}

// ---------------- GEMM: C[M,128] = A[M,128] * B[128,128], fp32 ----------------
__global__ void gemm128(const float* __restrict__ A, const float* __restrict__ B,
                        float* __restrict__ C, int M) {
    __shared__ __align__(16) float As[64][36];
    __shared__ __align__(16) float Bs[32][68];
    int tid = threadIdx.x, tx = tid & 15, ty = tid >> 4;
    int m0 = blockIdx.x * 64, n0 = blockIdx.y * 64;
    float acc[4][4] = {};
    for (int kk = 0; kk < 4; kk++) {
        int k0 = kk * 32;
        #pragma unroll
        for (int j = 0; j < 2; j++) {
            int idx = tid + j * 256;
            int r = idx >> 3, k4 = idx & 7;
            float4 v = make_float4(0.f, 0.f, 0.f, 0.f);
            int row = m0 + r;
            if (row < M) v = *(const float4*)(A + row * 128 + k0 + k4 * 4);
            *(float4*)&As[r][k4 * 4] = v;
        }
        #pragma unroll
        for (int j = 0; j < 2; j++) {
            int idx = tid + j * 256;
            int k = idx >> 4, c4 = idx & 15;
            float4 v = *(const float4*)(B + (k0 + k) * 128 + n0 + c4 * 4);
            *(float4*)&Bs[k][c4 * 4] = v;
        }
        __syncthreads();
        #pragma unroll
        for (int k = 0; k < 32; k++) {
            float4 b = *(const float4*)&Bs[k][tx * 4];
            #pragma unroll
            for (int i = 0; i < 4; i++) {
                float a = As[ty * 4 + i][k];
                acc[i][0] += a * b.x; acc[i][1] += a * b.y;
                acc[i][2] += a * b.z; acc[i][3] += a * b.w;
            }
        }
        __syncthreads();
    }
    #pragma unroll
    for (int i = 0; i < 4; i++) {
        int row = m0 + ty * 4 + i;
        if (row < M)
            *(float4*)(C + row * 128 + n0 + tx * 4) =
                make_float4(acc[i][0], acc[i][1], acc[i][2], acc[i][3]);
    }
}

// ---------------- per-node attention coefficients ----------------
__global__ void alpha1_kernel(const float* __restrict__ h,
                              const float* __restrict__ a_src,
                              const float* __restrict__ a_dst, int n) {
    int w = (blockIdx.x * blockDim.x + threadIdx.x) >> 5;
    int lane = threadIdx.x & 31;
    if (w >= n) return;
    const float* hp = h + w * 128;
    float h0 = hp[lane], h1v = hp[lane + 32], h2v = hp[lane + 64], h3v = hp[lane + 96];
    float s0 = h0 * a_src[lane],      s1 = h1v * a_src[lane + 32];
    float s2 = h2v * a_src[lane + 64], s3 = h3v * a_src[lane + 96];
    float d0 = h0 * a_dst[lane],      d1 = h1v * a_dst[lane + 32];
    float d2 = h2v * a_dst[lane + 64], d3 = h3v * a_dst[lane + 96];
    #pragma unroll
    for (int o = 16; o; o >>= 1) {
        s0 += __shfl_xor_sync(FULL_M, s0, o); s1 += __shfl_xor_sync(FULL_M, s1, o);
        s2 += __shfl_xor_sync(FULL_M, s2, o); s3 += __shfl_xor_sync(FULL_M, s3, o);
        d0 += __shfl_xor_sync(FULL_M, d0, o); d1 += __shfl_xor_sync(FULL_M, d1, o);
        d2 += __shfl_xor_sync(FULL_M, d2, o); d3 += __shfl_xor_sync(FULL_M, d3, o);
    }
    if (lane == 0) {
        g_as1[w] = make_float4(s0, s1, s2, s3);
        g_ad1[w] = make_float4(d0, d1, d2, d3);
    }
}

__global__ void alpha2_kernel(const float* __restrict__ h,
                              const float* __restrict__ a_src,
                              const float* __restrict__ a_dst, int n) {
    int w = (blockIdx.x * blockDim.x + threadIdx.x) >> 5;
    int lane = threadIdx.x & 31;
    if (w >= n) return;
    const float* hp = h + w * 128;
    float s = hp[lane] * a_src[lane] + hp[lane + 32] * a_src[lane + 32]
            + hp[lane + 64] * a_src[lane + 64] + hp[lane + 96] * a_src[lane + 96];
    float d = hp[lane] * a_dst[lane] + hp[lane + 32] * a_dst[lane + 32]
            + hp[lane + 64] * a_dst[lane + 64] + hp[lane + 96] * a_dst[lane + 96];
    #pragma unroll
    for (int o = 16; o; o >>= 1) {
        s += __shfl_xor_sync(FULL_M, s, o);
        d += __shfl_xor_sync(FULL_M, d, o);
    }
    if (lane == 0) { g_as2[w] = s; g_ad2[w] = d; }
}

// ---------------- layer-1 aggregation (4 heads x 32 ch) + bias + ELU ----------------
__global__ void agg1_kernel(const float* __restrict__ h,
                            const float* __restrict__ b1,
                            float* __restrict__ out, int n) {
    int w = (blockIdx.x * blockDim.x + threadIdx.x) >> 5;
    int lane = threadIdx.x & 31;
    if (w >= n) return;
    int beg = g_rowptr[w], end = g_rowptr[w + 1];
    float4 ad = g_ad1[w];

    // pass 1: per-head segment max (self loop guarantees end > beg)
    float m0 = -1e30f, m1 = -1e30f, m2 = -1e30f, m3 = -1e30f;
    for (int i = beg + lane; i < end; i += 32) {
        float4 a = g_as1[g_csr_src[i]];
        m0 = fmaxf(m0, lrelu(a.x + ad.x));
        m1 = fmaxf(m1, lrelu(a.y + ad.y));
        m2 = fmaxf(m2, lrelu(a.z + ad.z));
        m3 = fmaxf(m3, lrelu(a.w + ad.w));
    }
    #pragma unroll
    for (int o = 16; o; o >>= 1) {
        m0 = fmaxf(m0, __shfl_xor_sync(FULL_M, m0, o));
        m1 = fmaxf(m1, __shfl_xor_sync(FULL_M, m1, o));
        m2 = fmaxf(m2, __shfl_xor_sync(FULL_M, m2, o));
        m3 = fmaxf(m3, __shfl_xor_sync(FULL_M, m3, o));
    }

    // pass 2: exp weights + feature accumulation + denominator
    float acc0 = 0.f, acc1 = 0.f, acc2 = 0.f, acc3 = 0.f;
    float dn0 = 0.f, dn1 = 0.f, dn2 = 0.f, dn3 = 0.f;
    for (int g = beg; g < end; g += 32) {
        int i = g + lane;
        float e0 = 0.f, e1 = 0.f, e2 = 0.f, e3 = 0.f;
        int s = 0;
        if (i < end) {
            s = g_csr_src[i];
            float4 a = g_as1[s];
            e0 = __expf(lrelu(a.x + ad.x) - m0);
            e1 = __expf(lrelu(a.y + ad.y) - m1);
            e2 = __expf(lrelu(a.z + ad.z) - m2);
            e3 = __expf(lrelu(a.w + ad.w) - m3);
        }
        dn0 += e0; dn1 += e1; dn2 += e2; dn3 += e3;
        #pragma unroll
        for (int j = 0; j < 32; j++) {
            float f0 = __shfl_sync(FULL_M, e0, j);
            float f1 = __shfl_sync(FULL_M, e1, j);
            float f2 = __shfl_sync(FULL_M, e2, j);
            float f3 = __shfl_sync(FULL_M, e3, j);
            int  sj = __shfl_sync(FULL_M, s, j);
            if (f0 + f1 + f2 + f3 > 0.f) {
                const float* hp = h + sj * 128;
                acc0 += f0 * hp[lane];
                acc1 += f1 * hp[lane + 32];
                acc2 += f2 * hp[lane + 64];
                acc3 += f3 * hp[lane + 96];
            }
        }
    }
    #pragma unroll
    for (int o = 16; o; o >>= 1) {
        dn0 += __shfl_xor_sync(FULL_M, dn0, o);
        dn1 += __shfl_xor_sync(FULL_M, dn1, o);
        dn2 += __shfl_xor_sync(FULL_M, dn2, o);
        dn3 += __shfl_xor_sync(FULL_M, dn3, o);
    }
    float v0 = acc0 / (dn0 + EPS_) + b1[lane];
    float v1 = acc1 / (dn1 + EPS_) + b1[lane + 32];
    float v2 = acc2 / (dn2 + EPS_) + b1[lane + 64];
    float v3 = acc3 / (dn3 + EPS_) + b1[lane + 96];
    float* op = out + w * 128;
    op[lane]      = v0 > 0.f ? v0 : expm1f(v0);   // ELU(alpha=1)
    op[lane + 32] = v1 > 0.f ? v1 : expm1f(v1);
    op[lane + 64] = v2 > 0.f ? v2 : expm1f(v2);
    op[lane + 96] = v3 > 0.f ? v3 : expm1f(v3);
}

// ---------------- layer-2 aggregation (1 head x 128 ch) + bias ----------------
__global__ void agg2_kernel(const float* __restrict__ h,
                            const float* __restrict__ b2,
                            float* __restrict__ out, int n) {
    int w = (blockIdx.x * blockDim.x + threadIdx.x) >> 5;
    int lane = threadIdx.x & 31;
    if (w >= n) return;
    int beg = g_rowptr[w], end = g_rowptr[w + 1];
    float adn = g_ad2[w];

    float m = -1e30f;
    for (int i = beg + lane; i < end; i += 32)
        m = fmaxf(m, lrelu(g_as2[g_csr_src[i]] + adn));
    #pragma unroll
    for (int o = 16; o; o >>= 1)
        m = fmaxf(m, __shfl_xor_sync(FULL_M, m, o));

    float acc0 = 0.f, acc1 = 0.f, acc2 = 0.f, acc3 = 0.f, dn = 0.f;
    for (int g = beg; g < end; g += 32) {
        int i = g + lane;
        float e = 0.f; int s = 0;
        if (i < end) {
            s = g_csr_src[i];
            e = __expf(lrelu(g_as2[s] + adn) - m);
        }
        dn += e;
        #pragma unroll
        for (int j = 0; j < 32; j++) {
            float f = __shfl_sync(FULL_M, e, j);
            int  sj = __shfl_sync(FULL_M, s, j);
            if (f > 0.f) {
                const float* hp = h + sj * 128;
                acc0 += f * hp[lane];
                acc1 += f * hp[lane + 32];
                acc2 += f * hp[lane + 64];
                acc3 += f * hp[lane + 96];
            }
        }
    }
    #pragma unroll
    for (int o = 16; o; o >>= 1)
        dn += __shfl_xor_sync(FULL_M, dn, o);
    float inv = 1.f / (dn + EPS_);
    float* op = out + w * 128;
    op[lane]      = acc0 * inv + b2[lane];
    op[lane + 32] = acc1 * inv + b2[lane + 32];
    op[lane + 64] = acc2 * inv + b2[lane + 64];
    op[lane + 96] = acc3 * inv + b2[lane + 96];
}

// ---------------- launch ----------------
extern "C" void kernel_launch(void* const* d_in, const int* in_sizes, int n_in,
                              void* d_out, int out_size) {
    const float* x     = (const float*)d_in[0];
    const int*   ei    = (const int*)d_in[1];
    const float* W1    = (const float*)d_in[2];
    const float* asrc1 = (const float*)d_in[3];
    const float* adst1 = (const float*)d_in[4];
    const float* b1    = (const float*)d_in[5];
    const float* W2    = (const float*)d_in[6];
    const float* asrc2 = (const float*)d_in[7];
    const float* adst2 = (const float*)d_in[8];
    const float* b2    = (const float*)d_in[9];
    float* out = (float*)d_out;

    int n = in_sizes[0] / 128;   // 30000
    int E = in_sizes[1] / 2;     // 480000

    float *p_h1, *p_act1, *p_h2;
    cudaGetSymbolAddress((void**)&p_h1,   g_h1);
    cudaGetSymbolAddress((void**)&p_act1, g_act1);
    cudaGetSymbolAddress((void**)&p_h2,   g_h2);

    // graph build (shared by both layers)
    init_kernel<<<(n + 255) / 256, 256>>>(n);
    hist_kernel<<<(E + 255) / 256, 256>>>(ei, E);
    scan_kernel<<<1, 1024>>>(n);
    scatter_kernel<<<(E + n + 255) / 256, 256>>>(ei, E, n);

    dim3 ggrid((n + 63) / 64, 2);
    int warp_blocks = (n * 32 + 255) / 256;

    // layer 1
    gemm128<<<ggrid, 256>>>(x, W1, p_h1, n);
    alpha1_kernel<<<warp_blocks, 256>>>(p_h1, asrc1, adst1, n);
    agg1_kernel<<<warp_blocks, 256>>>(p_h1, b1, p_act1, n);

    // layer 2
    gemm128<<<ggrid, 256>>>(p_act1, W2, p_h2, n);
    alpha2_kernel<<<warp_blocks, 256>>>(p_h2, asrc2, adst2, n);
    agg2_kernel<<<warp_blocks, 256>>>(p_h2, b2, out, n);
}